// round 9
// baseline (speedup 1.0000x reference)
#include <cuda_runtime.h>

#define NB 32
#define NC 64
#define NS 64
#define NE 6   // distinct experts (PERM folds 8 gates onto 6)

// Scratch (device globals)
__device__ float g_c  [4 * 16 * 64 * 32];          // [band][xy][i(chan)][b]
__device__ float g_S  [32 * 16 * 24 * 64];         // [b][xy][e*4+band][o]  (3MB)
__device__ float g_Wsum[NB];

// ---------------------------------------------------------------------------
// kA: pure x block-sum -> level-4 coefficient bands.  512 blocks x 256 thr,
// 4 (b,c) images per block.  Wsum in block 0.
// ---------------------------------------------------------------------------
__global__ void kA(const float* __restrict__ x, const float* __restrict__ lam) {
    __shared__ float ll3[4][64];
    int blk = blockIdx.x;
    int t = threadIdx.x;
    if (blk == 0 && t < 32) {
        const float* lp = lam + t * 8;
        g_Wsum[t] = lp[0]+lp[1]+lp[2]+lp[3]+lp[4]+lp[5]+lp[6]+lp[7];
    }
    int sub = t >> 6, tt = t & 63;
    int bc = (blk << 2) + sub;        // 0..2047
    int i = tt >> 3, j = tt & 7;
    const float* xp = x + (size_t)bc * NS * NS + (size_t)i * 8 * NS + j * 8;
    float s = 0.f;
#pragma unroll
    for (int r = 0; r < 8; r++) {
        float4 a = *(const float4*)(xp + r * NS);
        float4 b = *(const float4*)(xp + r * NS + 4);
        s += a.x + a.y + a.z + a.w + b.x + b.y + b.z + b.w;
    }
    ll3[sub][tt] = s * 0.125f;
    __syncthreads();
    if (tt < 16) {
        int xy = tt;
        int xx = xy >> 2, yy = xy & 3;
        float a = ll3[sub][(2 * xx) * 8 + 2 * yy];
        float b = ll3[sub][(2 * xx) * 8 + 2 * yy + 1];
        float c = ll3[sub][(2 * xx + 1) * 8 + 2 * yy];
        float d = ll3[sub][(2 * xx + 1) * 8 + 2 * yy + 1];
        int bb = bc >> 6, ch = bc & 63;
        float v[4];
        v[0] = (a + b + c + d) * 0.5f;
        v[1] = (a + b - c - d) * 0.5f;
        v[2] = (a - b + c - d) * 0.5f;
        v[3] = (a - b - c + d) * 0.5f;
#pragma unroll
        for (int band = 0; band < 4; band++)
            g_c[((band * 16 + xy) * 64 + ch) * 32 + bb] = v[band];
    }
}

// ---------------------------------------------------------------------------
// kB1: weights consumed DIRECTLY from original layout [i][o][xy] — one float4
// covers 4 xy.  Block = (band, e, xyq, bq): 192 blocks x 256 threads.
// Thread tile: 4xy x 2b x 2o.  c staged in smem (broadcast reads).
// Gate weight applied in epilogue; e==0 blocks subtract identity term.
// Output: g_S[b][xy][e*4+band][o].
// ---------------------------------------------------------------------------
__global__ void kB1(const float* __restrict__ WL, const float* __restrict__ WH,
                    const float* __restrict__ lam) {
    __shared__ float csh[4][64][16];              // [j][i][bl]  16KB
    int blk = blockIdx.x;             // = band*48 + e*8 + xyq*2 + bq
    int bq   = blk & 1;
    int xyq  = (blk >> 1) & 3;
    int e    = (blk >> 3) % NE;
    int band = blk / 48;
    int t = threadIdx.x;

    // stage c[xy][i][b] for 4 xy, 16 b (this bq half)
#pragma unroll
    for (int r = 0; r < 4; r++) {
        int idx = t + 256 * r;        // 0..1023
        int j = idx >> 8, i = (idx >> 2) & 63, blg = idx & 3;
        float4 v = *(const float4*)(g_c +
            ((size_t)((band * 16 + xyq * 4 + j) * 64 + i)) * 32 + bq * 16 + blg * 4);
        ((float4*)&csh[j][i][0])[blg] = v;
    }
    __syncthreads();

    const float* wsrc = (band == 0) ? WL + (size_t)e * 65536
                                    : WH + (size_t)(e * 3 + band - 1) * 65536;
    int og = t & 31;                  // o0 = og*2
    int bg = t >> 5;                  // b0 = bg*2 (local), 0..7
    int o0 = og * 2, b0 = bg * 2;
    const float* wp = wsrc + o0 * 16 + xyq * 4;   // + k*1024 per k

    float acc[4][2][2];
#pragma unroll
    for (int j = 0; j < 4; j++)
#pragma unroll
        for (int a = 0; a < 2; a++) { acc[j][a][0] = 0.f; acc[j][a][1] = 0.f; }

#pragma unroll 8
    for (int k = 0; k < 64; k++) {
        float4 wA = *(const float4*)(wp + (size_t)k * 1024);        // (k, o0, xy0..3)
        float4 wB = *(const float4*)(wp + (size_t)k * 1024 + 16);   // (k, o0+1)
        float wa[4] = {wA.x, wA.y, wA.z, wA.w};
        float wb[4] = {wB.x, wB.y, wB.z, wB.w};
#pragma unroll
        for (int j = 0; j < 4; j++) {
            float2 c2 = *(const float2*)&csh[j][k][b0];   // warp-broadcast
            acc[j][0][0] += c2.x * wa[j];
            acc[j][0][1] += c2.x * wb[j];
            acc[j][1][0] += c2.y * wa[j];
            acc[j][1][1] += c2.y * wb[j];
        }
    }

    // epilogue: gate scale (+ identity subtraction for e==0), store
    int B0 = bq * 16 + b0, B1 = B0 + 1;
    const float* lp0 = lam + B0 * 8;
    const float* lp1 = lam + B1 * 8;
    float we0, we1;
    if      (e == 0) { we0 = lp0[0];          we1 = lp1[0]; }
    else if (e == 1) { we0 = lp0[1];          we1 = lp1[1]; }
    else if (e == 2) { we0 = lp0[2];          we1 = lp1[2]; }
    else if (e == 3) { we0 = lp0[3];          we1 = lp1[3]; }
    else if (e == 4) { we0 = lp0[4] + lp0[6]; we1 = lp1[4] + lp1[6]; }
    else             { we0 = lp0[5] + lp0[7]; we1 = lp1[5] + lp1[7]; }
    float Wt0 = 0.f, Wt1 = 0.f;
    if (e == 0) { Wt0 = g_Wsum[B0]; Wt1 = g_Wsum[B1]; }

    int eb = e * 4 + band;
#pragma unroll
    for (int j = 0; j < 4; j++) {
        int xy = xyq * 4 + j;
        float r00 = acc[j][0][0] * we0, r01 = acc[j][0][1] * we0;
        float r10 = acc[j][1][0] * we1, r11 = acc[j][1][1] * we1;
        if (e == 0) {
            const float* cb = g_c + ((size_t)((band * 16 + xy) * 64)) * 32;
            r00 -= Wt0 * cb[(o0    ) * 32 + B0];
            r01 -= Wt0 * cb[(o0 + 1) * 32 + B0];
            r10 -= Wt1 * cb[(o0    ) * 32 + B1];
            r11 -= Wt1 * cb[(o0 + 1) * 32 + B1];
        }
        float* Sp = g_S + (((size_t)(B0 * 16 + xy)) * 24 + eb) * 64 + o0;
        *(float2*)Sp           = make_float2(r00, r01);
        *(float2*)(Sp + 24576) = make_float2(r10, r11);   // B1 (stride 16*24*64)
    }
}

// ---------------------------------------------------------------------------
// kC: fused expert-sum + IDWT + AXPY.  One block per (b,c) image.
// ---------------------------------------------------------------------------
__global__ void kC(const float* __restrict__ x, float* __restrict__ out) {
    __shared__ float zs[64];
    int bc = blockIdx.x;
    int t = threadIdx.x;
    int b = bc >> 6, c = bc & 63;

    if (t < 64) {
        int X = t >> 3, Y = t & 7;
        int xy = ((X >> 1) << 2) + (Y >> 1);
        float s1 = (X & 1) ? -1.f : 1.f;
        float s2 = (Y & 1) ? -1.f : 1.f;
        float s3 = s1 * s2;
        const float* p = g_S + ((size_t)(b * 16 + xy) * 24) * 64 + c;
        float z = 0.f;
#pragma unroll
        for (int e = 0; e < NE; e++) {
            float S0 = p[e * 256];
            float S1 = p[e * 256 + 64];
            float S2 = p[e * 256 + 128];
            float S3 = p[e * 256 + 192];
            z += S0 + s1 * S1 + s2 * S2 + s3 * S3;
        }
        zs[t] = z * 0.0625f;
    }
    float W = g_Wsum[b];
    __syncthreads();

    const float* xp = x + (size_t)bc * 4096;
    float* op = out + (size_t)bc * 4096;
#pragma unroll
    for (int k = 0; k < 4; k++) {
        int idx = (t << 2) + (k << 10);
        float zv = zs[((idx >> 9) << 3) + ((idx & 63) >> 3)];
        float4 xv = __ldcs((const float4*)(xp + idx));
        float4 ov;
        ov.x = fmaf(W, xv.x, zv);
        ov.y = fmaf(W, xv.y, zv);
        ov.z = fmaf(W, xv.z, zv);
        ov.w = fmaf(W, xv.w, zv);
        __stcs((float4*)(op + idx), ov);
    }
}

// ---------------------------------------------------------------------------
extern "C" void kernel_launch(void* const* d_in, const int* in_sizes, int n_in,
                              void* d_out, int out_size) {
    const float* x   = (const float*)d_in[0];  // [32,64,64,64]
    const float* lam = (const float*)d_in[1];  // [32,1,8,1]
    const float* WL  = (const float*)d_in[2];  // [8,64,64,4,4]
    const float* WH  = (const float*)d_in[3];  // [8,3,64,64,4,4]
    float* out = (float*)d_out;

    kA<<<512, 256>>>(x, lam);
    kB1<<<192, 256>>>(WL, WH, lam);
    kC<<<2048, 256>>>(x, out);
    (void)in_sizes; (void)n_in; (void)out_size;
}

// round 10
// speedup vs baseline: 1.7760x; 1.7760x over previous
#include <cuda_runtime.h>

#define NB 32
#define NC 64
#define NS 64
#define NE 6   // distinct experts (PERM folds 8 gates onto 6)

// Scratch (device globals)
__device__ float g_c  [4 * 16 * 64 * 32];          // [band][xy][i(chan)][b]
__device__ float g_Wt2[4 * 16 * NE * 64 * 64];     // [band][xy][e][i][o]  (6.3MB)
__device__ float g_S  [32 * 16 * 24 * 64];         // [b][xy][e*4+band][o]  (3MB)
__device__ float g_Wsum[NB];

// ---------------------------------------------------------------------------
// kTA: blocks 0..1023 = x block-sums (2 images/block, 128 thr/image, each
// thread sums 4 rows of one 8x8 cell -> 2x the warps in flight vs R7);
// blocks 1024..1407 = weight transpose; Wsum in block 1024.
// ---------------------------------------------------------------------------
__global__ void kTA(const float* __restrict__ x,
                    const float* __restrict__ WL, const float* __restrict__ WH,
                    const float* __restrict__ lam) {
    int blk = blockIdx.x;
    int t = threadIdx.x;              // 0..255
    if (blk < 1024) {
        __shared__ float part[2][128];
        __shared__ float ll3[2][64];
        int sub = t >> 7, tt = t & 127;
        int bc = (blk << 1) + sub;    // 0..2047
        int cell = tt >> 1;           // 0..63
        int half = tt & 1;
        int i = cell >> 3, j = cell & 7;
        const float* xp = x + (size_t)bc * 4096
                        + (size_t)(i * 8 + half * 4) * NS + j * 8;
        float s = 0.f;
#pragma unroll
        for (int r = 0; r < 4; r++) {
            float4 a = *(const float4*)(xp + r * NS);
            float4 b = *(const float4*)(xp + r * NS + 4);
            s += a.x + a.y + a.z + a.w + b.x + b.y + b.z + b.w;
        }
        part[sub][tt] = s;
        __syncthreads();
        if (tt < 64)
            ll3[sub][tt] = (part[sub][2 * tt] + part[sub][2 * tt + 1]) * 0.125f;
        __syncthreads();
        if (tt < 16) {
            int xy = tt;
            int xx = xy >> 2, yy = xy & 3;
            float a = ll3[sub][(2 * xx) * 8 + 2 * yy];
            float b = ll3[sub][(2 * xx) * 8 + 2 * yy + 1];
            float c = ll3[sub][(2 * xx + 1) * 8 + 2 * yy];
            float d = ll3[sub][(2 * xx + 1) * 8 + 2 * yy + 1];
            int bb = bc >> 6, ch = bc & 63;
            float v[4];
            v[0] = (a + b + c + d) * 0.5f;
            v[1] = (a + b - c - d) * 0.5f;
            v[2] = (a - b + c - d) * 0.5f;
            v[3] = (a - b - c + d) * 0.5f;
#pragma unroll
            for (int band = 0; band < 4; band++)
                g_c[((band * 16 + xy) * 64 + ch) * 32 + bb] = v[band];
        }
    } else {
        // ---- transpose W into [band][xy][e][i][o] ----
        int tb = blk - 1024;          // 0..383
        if (tb == 0 && t < 32) {
            const float* lp = lam + t * 8;
            g_Wsum[t] = lp[0]+lp[1]+lp[2]+lp[3]+lp[4]+lp[5]+lp[6]+lp[7];
        }
        int be = tb >> 4;             // band*6+e
        int rr = tb & 15;
        int band = be / NE, e = be % NE;
        const float* src;
        if (band == 0) src = WL + (size_t)e * 65536;
        else           src = WH + (size_t)(e * 3 + (band - 1)) * 65536;
        int io = t + 256 * rr;        // 0..4095
        const float* sp = src + (size_t)io * 16;
        float4 q0 = *(const float4*)(sp);
        float4 q1 = *(const float4*)(sp + 4);
        float4 q2 = *(const float4*)(sp + 8);
        float4 q3 = *(const float4*)(sp + 12);
        float v[16] = {q0.x,q0.y,q0.z,q0.w, q1.x,q1.y,q1.z,q1.w,
                       q2.x,q2.y,q2.z,q2.w, q3.x,q3.y,q3.z,q3.w};
        float* dbase = g_Wt2 + (size_t)band * 16 * 24576 + (size_t)e * 4096 + io;
#pragma unroll
        for (int xy = 0; xy < 16; xy++)
            dbase[(size_t)xy * 24576] = v[xy];
    }
}

// ---------------------------------------------------------------------------
// kB1: one block per (band,xy,e): S_e[b,o] = sum_i (w_e[b]*c[i,b]) * W_e[i,o]
// (e==0 blocks also subtract Wt[b]*c[o,b]).  384 blocks x 256 threads,
// 8KB smem LHS, K=64, thread tile 2b x 4o.  Output g_S[b][xy][e*4+band][o].
// ---------------------------------------------------------------------------
__global__ void kB1(const float* __restrict__ lam) {
    __shared__ float wcsh[64 * 32];               // 8KB: [i][b] gate-scaled
    int blk = blockIdx.x;             // 0..383
    int e = blk % NE;
    int bx = blk / NE;
    int xy = bx & 15;
    int band = bx >> 4;
    int t = threadIdx.x;
    int bl = t & 31;

    const float* lp = lam + bl * 8;
    float we;
    if      (e == 0) we = lp[0];
    else if (e == 1) we = lp[1];
    else if (e == 2) we = lp[2];
    else if (e == 3) we = lp[3];
    else if (e == 4) we = lp[4] + lp[6];
    else             we = lp[5] + lp[7];

    const float* cbase = g_c + (size_t)(band * 16 + xy) * 2048;   // [i][b]
#pragma unroll
    for (int r = 0; r < 8; r++) {
        int j = t + 256 * r;
        wcsh[j] = cbase[j] * we;
    }
    __syncthreads();

    int b0 = (t >> 4) * 2;            // 0..30
    int o0 = (t & 15) * 4;            // 0..60
    const float* wbase = g_Wt2 + ((size_t)(band * 16 + xy) * NE + e) * 4096 + o0;
    float a0x = 0.f, a0y = 0.f, a0z = 0.f, a0w = 0.f;
    float a1x = 0.f, a1y = 0.f, a1z = 0.f, a1w = 0.f;
#pragma unroll 8
    for (int k = 0; k < 64; k++) {
        float2 c2 = *(const float2*)(wcsh + k * 32 + b0);
        float4 w4 = *(const float4*)(wbase + k * 64);
        a0x += c2.x * w4.x; a0y += c2.x * w4.y; a0z += c2.x * w4.z; a0w += c2.x * w4.w;
        a1x += c2.y * w4.x; a1y += c2.y * w4.y; a1z += c2.y * w4.z; a1w += c2.y * w4.w;
    }

    if (e == 0) {
        float Wt0 = g_Wsum[b0], Wt1 = g_Wsum[b0 + 1];
        a0x -= Wt0 * cbase[(o0    ) * 32 + b0];
        a0y -= Wt0 * cbase[(o0 + 1) * 32 + b0];
        a0z -= Wt0 * cbase[(o0 + 2) * 32 + b0];
        a0w -= Wt0 * cbase[(o0 + 3) * 32 + b0];
        a1x -= Wt1 * cbase[(o0    ) * 32 + b0 + 1];
        a1y -= Wt1 * cbase[(o0 + 1) * 32 + b0 + 1];
        a1z -= Wt1 * cbase[(o0 + 2) * 32 + b0 + 1];
        a1w -= Wt1 * cbase[(o0 + 3) * 32 + b0 + 1];
    }

    int eb = e * 4 + band;
    float* Sp = g_S + (((size_t)(b0 * 16 + xy)) * 24 + eb) * 64 + o0;
    *(float4*)Sp            = make_float4(a0x, a0y, a0z, a0w);
    *(float4*)(Sp + 24576)  = make_float4(a1x, a1y, a1z, a1w);   // b0+1
}

// ---------------------------------------------------------------------------
// kC: fused expert-sum + IDWT + AXPY.  One block per (b,c) image.
// ---------------------------------------------------------------------------
__global__ void kC(const float* __restrict__ x, float* __restrict__ out) {
    __shared__ float zs[64];
    int bc = blockIdx.x;
    int t = threadIdx.x;
    int b = bc >> 6, c = bc & 63;

    if (t < 64) {
        int X = t >> 3, Y = t & 7;
        int xy = ((X >> 1) << 2) + (Y >> 1);
        float s1 = (X & 1) ? -1.f : 1.f;
        float s2 = (Y & 1) ? -1.f : 1.f;
        float s3 = s1 * s2;
        const float* p = g_S + ((size_t)(b * 16 + xy) * 24) * 64 + c;
        float z = 0.f;
#pragma unroll
        for (int e = 0; e < NE; e++) {
            float S0 = p[e * 256];
            float S1 = p[e * 256 + 64];
            float S2 = p[e * 256 + 128];
            float S3 = p[e * 256 + 192];
            z += S0 + s1 * S1 + s2 * S2 + s3 * S3;
        }
        zs[t] = z * 0.0625f;
    }
    float W = g_Wsum[b];
    __syncthreads();

    const float* xp = x + (size_t)bc * 4096;
    float* op = out + (size_t)bc * 4096;
#pragma unroll
    for (int k = 0; k < 4; k++) {
        int idx = (t << 2) + (k << 10);          // warp-contiguous within slot
        float zv = zs[((idx >> 9) << 3) + ((idx & 63) >> 3)];  // X*8 + Y
        float4 xv = *(const float4*)(xp + idx);
        float4 ov;
        ov.x = fmaf(W, xv.x, zv);
        ov.y = fmaf(W, xv.y, zv);
        ov.z = fmaf(W, xv.z, zv);
        ov.w = fmaf(W, xv.w, zv);
        *(float4*)(op + idx) = ov;
    }
}

// ---------------------------------------------------------------------------
extern "C" void kernel_launch(void* const* d_in, const int* in_sizes, int n_in,
                              void* d_out, int out_size) {
    const float* x   = (const float*)d_in[0];  // [32,64,64,64]
    const float* lam = (const float*)d_in[1];  // [32,1,8,1]
    const float* WL  = (const float*)d_in[2];  // [8,64,64,4,4]
    const float* WH  = (const float*)d_in[3];  // [8,3,64,64,4,4]
    float* out = (float*)d_out;

    kTA<<<1408, 256>>>(x, WL, WH, lam);
    kB1<<<384, 256>>>(lam);
    kC<<<2048, 256>>>(x, out);
    (void)in_sizes; (void)n_in; (void)out_size;
}